// round 10
// baseline (speedup 1.0000x reference)
#include <cuda_runtime.h>

constexpr int NMAX  = 100000;
constexpr int EMAX  = 1600000;
constexpr int D_IN  = 16;
constexpr int D_HID = 32;
constexpr int D_OUT = 16;

// Scratch (__device__ globals; allocation-free rule). Zero-initialized at load.
__device__ alignas(16) float g_pre[NMAX * D_IN];   // emb[x[v]] * dinv[v]
__device__ alignas(16) float g_a  [NMAX * D_IN];   // conv1 pre-GEMM: dinv*(sum+self)
__device__ alignas(16) float g_hs2[NMAX * D_OUT];  // (relu(a@W1+b1)@W2) * dinv
__device__ float g_dinv[NMAX];
__device__ int   g_deg [NMAX];   // 0 at entry (static init / reset by k_build)
__device__ int   g_row [NMAX];   // CSR bucket start (by dst)
__device__ int   g_cur [NMAX];   // fill cursor; == bucket end after k_fill
__device__ int   g_csr [EMAX];   // src per CSR slot
__device__ int   g_ctr;          // bucket allocator (reset by k_deg)

// ---------------------------------------------------------------------------
// K1: degree histogram over real edges; also resets the bucket allocator.
__global__ void k_deg(const int* __restrict__ dst, int E) {
    if (blockIdx.x == 0 && threadIdx.x == 0) g_ctr = 0;
    int i = blockIdx.x * blockDim.x + threadIdx.x;
    int e4 = i * 4;
    if (e4 + 3 < E) {
        int4 d = *reinterpret_cast<const int4*>(dst + e4);
        atomicAdd(&g_deg[d.x], 1); atomicAdd(&g_deg[d.y], 1);
        atomicAdd(&g_deg[d.z], 1); atomicAdd(&g_deg[d.w], 1);
    } else {
        for (int e = e4; e < E && e >= 0; e++) atomicAdd(&g_deg[dst[e]], 1);
    }
}

// K2: per block: smem scan of 256 degrees + ONE atomicAdd on g_ctr for the
//     block base (bucket order across blocks is irrelevant — only disjointness
//     matters). Also: dinv, pre = emb[x[v]]*dinv, deg reset.
__global__ void k_build(const int* __restrict__ x, const float* __restrict__ emb,
                        int n) {
    __shared__ int sm[256];
    __shared__ int base_s;
    int v = blockIdx.x * 256 + threadIdx.x;
    int d = (v < n) ? g_deg[v] : 0;

    sm[threadIdx.x] = d;
    __syncthreads();
#pragma unroll
    for (int o = 1; o < 256; o <<= 1) {
        int t = (threadIdx.x >= o) ? sm[threadIdx.x - o] : 0;
        __syncthreads();
        sm[threadIdx.x] += t;
        __syncthreads();
    }
    int incl = sm[threadIdx.x];
    if (threadIdx.x == 255) base_s = atomicAdd(&g_ctr, incl);
    __syncthreads();

    if (v < n) {
        int start = base_s + incl - d;
        g_row[v] = start;
        g_cur[v] = start;
        g_deg[v] = 0;                          // reset for next replay
        float dinv = rsqrtf((float)(d + 1));   // +1 self-loop
        g_dinv[v] = dinv;
        int xr = __ldg(&x[v]);
        const float4* er = reinterpret_cast<const float4*>(emb) + (size_t)xr * 4;
        float4* pr = reinterpret_cast<float4*>(g_pre) + (size_t)v * 4;
#pragma unroll
        for (int q = 0; q < 4; q++) {
            float4 e = er[q];
            pr[q] = make_float4(e.x * dinv, e.y * dinv, e.z * dinv, e.w * dinv);
        }
    }
}

// K3: bucket fill: csr[pos] = src for each edge, bucketed by dst.
__global__ void k_fill(const int* __restrict__ src, const int* __restrict__ dst,
                       int E) {
    int e = blockIdx.x * blockDim.x + threadIdx.x;
    if (e >= E) return;
    int d = __ldg(&dst[e]);
    int pos = atomicAdd(&g_cur[d], 1);
    g_csr[pos] = __ldg(&src[e]);
}

// K4/K6: gather aggregation, warp per node. chunk = lane&3 (float4 of the
//     16-float row), sub = lane>>2 (8 neighbors in flight). Epilogue:
//     LAYER 1: g_a = dinv*(sum + pre[v]);  LAYER 2: out = dinv*(sum+hs2[v])+b2.
template <int LAYER>
__global__ void k_agg(const float* __restrict__ b2, float* __restrict__ out,
                      int n) {
    const float* in = (LAYER == 1) ? g_pre : g_hs2;

    int gw = (blockIdx.x * blockDim.x + threadIdx.x) >> 5;
    if (gw >= n) return;
    int v = gw;
    int lane = threadIdx.x & 31;
    int chunk = lane & 3;
    int sub   = lane >> 2;

    int start = g_row[v], end = g_cur[v];
    float4 acc = make_float4(0.f, 0.f, 0.f, 0.f);
    for (int j = start + sub; j < end; j += 8) {
        int s = __ldg(&g_csr[j]);
        float4 t = reinterpret_cast<const float4*>(in)[(size_t)s * 4 + chunk];
        acc.x += t.x; acc.y += t.y; acc.z += t.z; acc.w += t.w;
    }
#pragma unroll
    for (int o = 4; o <= 16; o <<= 1) {
        acc.x += __shfl_xor_sync(~0u, acc.x, o);
        acc.y += __shfl_xor_sync(~0u, acc.y, o);
        acc.z += __shfl_xor_sync(~0u, acc.z, o);
        acc.w += __shfl_xor_sync(~0u, acc.w, o);
    }
    if (sub == 0) {
        float dinv = g_dinv[v];
        float4 self = reinterpret_cast<const float4*>(in)[(size_t)v * 4 + chunk];
        if (LAYER == 1) {
            reinterpret_cast<float4*>(g_a)[(size_t)v * 4 + chunk] =
                make_float4(dinv * (acc.x + self.x), dinv * (acc.y + self.y),
                            dinv * (acc.z + self.z), dinv * (acc.w + self.w));
        } else {
            float4 bb = __ldg(reinterpret_cast<const float4*>(b2) + chunk);
            reinterpret_cast<float4*>(out)[(size_t)v * 4 + chunk] =
                make_float4(dinv * (acc.x + self.x) + bb.x,
                            dinv * (acc.y + self.y) + bb.y,
                            dinv * (acc.z + self.z) + bb.z,
                            dinv * (acc.w + self.w) + bb.w);
        }
    }
}

// K5: TWO threads per node (pair = lanes xor 1). Lane p owns W1 columns
//     [16p,16p+16) and W2 rows [16p,16p+16). Input g_a is pre-normalized.
//     hs2 = (relu(a@W1+b1)@W2) * dinv.
__global__ void k_mid(const float* __restrict__ W1, const float* __restrict__ b1,
                      const float* __restrict__ W2, int n) {
    __shared__ float4 W1s[D_IN * (D_HID / 4)];   // [k][j4] 16 x 8
    __shared__ float4 W2s[D_HID * (D_OUT / 4)];  // [k][j4] 32 x 4
    __shared__ float4 b1s[D_HID / 4];
    for (int t = threadIdx.x; t < D_IN * D_HID / 4; t += blockDim.x)
        W1s[t] = reinterpret_cast<const float4*>(W1)[t];
    for (int t = threadIdx.x; t < D_HID * D_OUT / 4; t += blockDim.x)
        W2s[t] = reinterpret_cast<const float4*>(W2)[t];
    if (threadIdx.x < D_HID / 4)
        b1s[threadIdx.x] = reinterpret_cast<const float4*>(b1)[threadIdx.x];
    __syncthreads();

    int t = blockIdx.x * blockDim.x + threadIdx.x;
    int v = t >> 1, p = t & 1;
    if (v >= n) return;

    float dinv = g_dinv[v];
    const float4* ar = reinterpret_cast<const float4*>(g_a + (size_t)v * D_IN);
    float4 a0 = ar[2 * p], a1 = ar[2 * p + 1];
    float al[8] = {a0.x, a0.y, a0.z, a0.w, a1.x, a1.y, a1.z, a1.w};

    // Build full a[16]: lane p owns a[8p..8p+8); partner supplies the rest.
    float a[D_IN];
    bool hi = (p != 0);
#pragma unroll
    for (int i = 0; i < 8; i++) {
        float theirs = __shfl_xor_sync(~0u, al[i], 1);
        a[i]     = hi ? theirs : al[i];
        a[8 + i] = hi ? al[i] : theirs;
    }

    // r[16] = relu(b1 + a @ W1)[16p .. 16p+16).
    int jb = 4 * p;
    float r[16];
#pragma unroll
    for (int j4 = 0; j4 < 4; j4++) {
        float4 b = b1s[jb + j4];
        r[j4*4+0] = b.x; r[j4*4+1] = b.y; r[j4*4+2] = b.z; r[j4*4+3] = b.w;
    }
#pragma unroll
    for (int k = 0; k < D_IN; k++) {
        float ak = a[k];
#pragma unroll
        for (int j4 = 0; j4 < 4; j4++) {
            float4 w = W1s[k * (D_HID / 4) + jb + j4];
            r[j4*4+0] = fmaf(ak, w.x, r[j4*4+0]);
            r[j4*4+1] = fmaf(ak, w.y, r[j4*4+1]);
            r[j4*4+2] = fmaf(ak, w.z, r[j4*4+2]);
            r[j4*4+3] = fmaf(ak, w.w, r[j4*4+3]);
        }
    }
#pragma unroll
    for (int j = 0; j < 16; j++) r[j] = fmaxf(r[j], 0.f);

    // Partial h over my 16 W2 rows [16p .. 16p+16).
    int kb = 16 * p;
    float ph[D_OUT];
#pragma unroll
    for (int j = 0; j < D_OUT; j++) ph[j] = 0.f;
#pragma unroll
    for (int kk = 0; kk < 16; kk++) {
        float rv = r[kk];
#pragma unroll
        for (int j4 = 0; j4 < 4; j4++) {
            float4 w = W2s[(kb + kk) * (D_OUT / 4) + j4];
            ph[j4*4+0] = fmaf(rv, w.x, ph[j4*4+0]);
            ph[j4*4+1] = fmaf(rv, w.y, ph[j4*4+1]);
            ph[j4*4+2] = fmaf(rv, w.z, ph[j4*4+2]);
            ph[j4*4+3] = fmaf(rv, w.w, ph[j4*4+3]);
        }
    }

    // Combine: lane p keeps final h[8p .. 8p+8), scaled by dinv.
    float h[8];
#pragma unroll
    for (int i = 0; i < 8; i++) {
        float send = hi ? ph[i] : ph[8 + i];
        float recv = __shfl_xor_sync(~0u, send, 1);
        h[i] = ((hi ? ph[8 + i] : ph[i]) + recv) * dinv;
    }

    size_t off = (size_t)v * D_OUT + 8 * p;
    *reinterpret_cast<float4*>(g_hs2 + off)     = make_float4(h[0], h[1], h[2], h[3]);
    *reinterpret_cast<float4*>(g_hs2 + off + 4) = make_float4(h[4], h[5], h[6], h[7]);
}

extern "C" void kernel_launch(void* const* d_in, const int* in_sizes, int n_in,
                              void* d_out, int out_size) {
    const int*   x   = (const int*)  d_in[0];
    const int*   ei  = (const int*)  d_in[1];   // [2, E]: src then dst
    const float* emb = (const float*)d_in[2];
    const float* W1  = (const float*)d_in[3];
    const float* b1  = (const float*)d_in[4];
    const float* W2  = (const float*)d_in[5];
    const float* b2  = (const float*)d_in[6];
    float* out = (float*)d_out;

    int n = in_sizes[0];
    int E = in_sizes[1] / 2;
    const int* src = ei;
    const int* dst = ei + E;

    const int B = 256;
    int nb_warp = (n * 32 + B - 1) / B;

    k_deg   <<<(E / 4 + B - 1) / B + 1, B>>>(dst, E);
    k_build <<<(n + 255) / 256, 256>>>(x, emb, n);
    k_fill  <<<(E + B - 1) / B, B>>>(src, dst, E);
    k_agg<1><<<nb_warp, B>>>(nullptr, nullptr, n);
    k_mid   <<<(n * 2 + B - 1) / B, B>>>(W1, b1, W2, n);
    k_agg<2><<<nb_warp, B>>>(b2, out, n);
}

// round 11
// speedup vs baseline: 1.1041x; 1.1041x over previous
#include <cuda_runtime.h>

constexpr int NMAX  = 100000;
constexpr int D_IN  = 16;
constexpr int D_HID = 32;
constexpr int D_OUT = 16;

// Weights in constant memory (filled per-call via D2D cudaMemcpyToSymbolAsync;
// graph-capturable, allocation-free).
__constant__ float c_W1[D_IN * D_HID];
__constant__ float c_W2[D_HID * D_OUT];
__constant__ float c_b1[D_HID];
__constant__ float c_b2[D_OUT];

// Scratch (__device__ globals; allocation-free rule). Zero-initialized at load.
__device__ alignas(16) float g_pre [NMAX * D_IN];   // emb[x[v]] * dinv[v]
__device__ alignas(16) float g_agg1[NMAX * D_IN];   // self + Sum over in-edges
__device__ alignas(16) float g_hs2 [NMAX * D_OUT];  // (relu(conv1)@W2) * dinv
__device__ alignas(16) float g_agg2[NMAX * D_OUT];  // self + Sum over in-edges
__device__ float g_dinv[NMAX];
__device__ int   g_deg [NMAX];   // 0 at entry (static init / reset by k_pre)

// ---------------------------------------------------------------------------
// K1: degree histogram over real edges (self-loop folded as +1 in k_pre).
__global__ void k_deg(const int* __restrict__ dst, int E) {
    int i = blockIdx.x * blockDim.x + threadIdx.x;
    int e4 = i * 4;
    if (e4 + 3 < E) {
        int4 d = *reinterpret_cast<const int4*>(dst + e4);
        atomicAdd(&g_deg[d.x], 1); atomicAdd(&g_deg[d.y], 1);
        atomicAdd(&g_deg[d.z], 1); atomicAdd(&g_deg[d.w], 1);
    } else {
        for (int e = e4; e < E && e >= 0; e++) atomicAdd(&g_deg[dst[e]], 1);
    }
}

// K2: 4 threads per node (one float4 chunk each): dinv; pre = emb[x[v]]*dinv;
//     agg1 = pre (self-loop seed); reset deg. Node's 4 threads share a warp
//     and are convergent at the load, so read-before-lane0-reset is race-free.
__global__ void k_pre(const int* __restrict__ x, const float* __restrict__ emb,
                      int n) {
    int t = blockIdx.x * blockDim.x + threadIdx.x;
    int v = t >> 2, q = t & 3;
    if (v >= n) return;
    int d = g_deg[v];
    float dinv = rsqrtf((float)(d + 1));
    if (q == 0) { g_deg[v] = 0; g_dinv[v] = dinv; }
    int xr = __ldg(&x[v]);
    float4 e = reinterpret_cast<const float4*>(emb)[(size_t)xr * 4 + q];
    float4 p = make_float4(e.x * dinv, e.y * dinv, e.z * dinv, e.w * dinv);
    reinterpret_cast<float4*>(g_pre )[(size_t)v * 4 + q] = p;
    reinterpret_cast<float4*>(g_agg1)[(size_t)v * 4 + q] = p;
}

// K3/K5: edge scatter in 16-dim space: 4 threads per edge, red.v4 per thread.
template <int LAYER>
__global__ void k_scatter(const int* __restrict__ src, const int* __restrict__ dst,
                          int E) {
    const float* in  = (LAYER == 1) ? g_pre  : g_hs2;
    float*       out = (LAYER == 1) ? g_agg1 : g_agg2;

    long long t = (long long)blockIdx.x * blockDim.x + threadIdx.x;
    int e = (int)(t >> 2);
    if (e >= E) return;
    int c = (int)t & 3;

    int s = __ldg(&src[e]);
    int d = __ldg(&dst[e]);

    float4 v = *reinterpret_cast<const float4*>(in + ((size_t)s << 4) + c * 4);
    float* p = out + ((size_t)d << 4) + c * 4;
    asm volatile("red.global.add.v4.f32 [%0], {%1,%2,%3,%4};"
                 :: "l"(p), "f"(v.x), "f"(v.y), "f"(v.z), "f"(v.w) : "memory");
}

// K4: thread per node; ALL weights from __constant__ with compile-time
//     offsets (uniform-constant port, no shared, no syncthreads).
//     a = agg1*dinv; r = relu(a@W1+b1); hs2 = agg2 = (r@W2)*dinv.
__global__ __launch_bounds__(128) void k_mid(int n) {
    int v = blockIdx.x * blockDim.x + threadIdx.x;
    if (v >= n) return;

    float dinv = g_dinv[v];
    float a[D_IN];
    const float4* ar = reinterpret_cast<const float4*>(g_agg1 + (size_t)v * D_IN);
#pragma unroll
    for (int q = 0; q < D_IN / 4; q++) {
        float4 t = ar[q];
        a[q*4+0] = t.x * dinv; a[q*4+1] = t.y * dinv;
        a[q*4+2] = t.z * dinv; a[q*4+3] = t.w * dinv;
    }

    float r[D_HID];
#pragma unroll
    for (int j = 0; j < D_HID; j++) r[j] = c_b1[j];
#pragma unroll
    for (int k = 0; k < D_IN; k++) {
        float ak = a[k];
#pragma unroll
        for (int j = 0; j < D_HID; j++)
            r[j] = fmaf(ak, c_W1[k * D_HID + j], r[j]);
    }
#pragma unroll
    for (int j = 0; j < D_HID; j++) r[j] = fmaxf(r[j], 0.f);

    float h[D_OUT];
#pragma unroll
    for (int j = 0; j < D_OUT; j++) h[j] = 0.f;
#pragma unroll
    for (int k = 0; k < D_HID; k++) {
        float rv = r[k];
#pragma unroll
        for (int j = 0; j < D_OUT; j++)
            h[j] = fmaf(rv, c_W2[k * D_OUT + j], h[j]);
    }

    float4* hr = reinterpret_cast<float4*>(g_hs2  + (size_t)v * D_OUT);
    float4* gr = reinterpret_cast<float4*>(g_agg2 + (size_t)v * D_OUT);
#pragma unroll
    for (int q = 0; q < D_OUT / 4; q++) {
        float4 t = make_float4(h[q*4+0]*dinv, h[q*4+1]*dinv,
                               h[q*4+2]*dinv, h[q*4+3]*dinv);
        hr[q] = t;
        gr[q] = t;
    }
}

// K6: 4 threads per node: out = agg2*dinv + b2 (bias from constant memory).
__global__ void k_post(float* __restrict__ out, int n) {
    int t = blockIdx.x * blockDim.x + threadIdx.x;
    int v = t >> 2, q = t & 3;
    if (v >= n) return;
    float dinv = g_dinv[v];
    float4 a = reinterpret_cast<const float4*>(g_agg2)[(size_t)v * 4 + q];
    reinterpret_cast<float4*>(out)[(size_t)v * 4 + q] =
        make_float4(dinv * a.x + c_b2[q*4+0], dinv * a.y + c_b2[q*4+1],
                    dinv * a.z + c_b2[q*4+2], dinv * a.w + c_b2[q*4+3]);
}

extern "C" void kernel_launch(void* const* d_in, const int* in_sizes, int n_in,
                              void* d_out, int out_size) {
    const int*   x   = (const int*)  d_in[0];
    const int*   ei  = (const int*)  d_in[1];   // [2, E]: src then dst
    const float* emb = (const float*)d_in[2];
    const float* W1  = (const float*)d_in[3];
    const float* b1  = (const float*)d_in[4];
    const float* W2  = (const float*)d_in[5];
    const float* b2  = (const float*)d_in[6];
    float* out = (float*)d_out;

    int n = in_sizes[0];
    int E = in_sizes[1] / 2;
    const int* src = ei;
    const int* dst = ei + E;

    // Stage weights into constant memory (D2D async copies; graph-capturable).
    cudaMemcpyToSymbolAsync(c_W1, W1, D_IN  * D_HID * sizeof(float), 0,
                            cudaMemcpyDeviceToDevice);
    cudaMemcpyToSymbolAsync(c_W2, W2, D_HID * D_OUT * sizeof(float), 0,
                            cudaMemcpyDeviceToDevice);
    cudaMemcpyToSymbolAsync(c_b1, b1, D_HID * sizeof(float), 0,
                            cudaMemcpyDeviceToDevice);
    cudaMemcpyToSymbolAsync(c_b2, b2, D_OUT * sizeof(float), 0,
                            cudaMemcpyDeviceToDevice);

    const int B = 256;
    long long et = (long long)E * 4;
    int nb_edge  = (int)((et + B - 1) / B);
    int nb_node4 = (n * 4 + B - 1) / B;

    k_deg       <<<(E / 4 + B - 1) / B + 1, B>>>(dst, E);
    k_pre       <<<nb_node4, B>>>(x, emb, n);
    k_scatter<1><<<nb_edge, B>>>(src, dst, E);
    k_mid       <<<(n + 127) / 128, 128>>>(n);
    k_scatter<2><<<nb_edge, B>>>(src, dst, E);
    k_post      <<<nb_node4, B>>>(out, n);
}

// round 13
// speedup vs baseline: 1.1782x; 1.0671x over previous
#include <cuda_runtime.h>

constexpr int NMAX  = 100000;
constexpr int D_IN  = 16;
constexpr int D_HID = 32;
constexpr int D_OUT = 16;

#define PACK_F32X2(out, lo, hi) \
    asm("mov.b64 %0, {%1, %2};" : "=l"(out) : "f"(lo), "f"(hi))
#define UNPACK_F32X2(lo, hi, in) \
    asm("mov.b64 {%0, %1}, %2;" : "=f"(lo), "=f"(hi) : "l"(in))
#define FMA_F32X2(d, a, b, c) \
    asm("fma.rn.f32x2 %0, %1, %2, %3;" : "=l"(d) : "l"(a), "l"(b), "l"(c))

// Scratch (__device__ globals; allocation-free rule). Zero-initialized at load.
__device__ alignas(16) float g_pre [NMAX * D_IN];   // emb[x[v]] * dinv[v]
__device__ alignas(16) float g_agg1[NMAX * D_IN];   // self + Sum over in-edges
__device__ alignas(16) float g_hs2 [NMAX * D_OUT];  // (relu(conv1)@W2) * dinv
__device__ alignas(16) float g_agg2[NMAX * D_OUT];  // self + Sum over in-edges
__device__ float g_dinv[NMAX];
__device__ int   g_deg [NMAX];   // 0 at entry (static init / reset by k_pre)

// ---------------------------------------------------------------------------
// K1: degree histogram over real edges (self-loop folded as +1 in k_pre).
__global__ void k_deg(const int* __restrict__ dst, int E) {
    int i = blockIdx.x * blockDim.x + threadIdx.x;
    int e4 = i * 4;
    if (e4 + 3 < E) {
        int4 d = *reinterpret_cast<const int4*>(dst + e4);
        atomicAdd(&g_deg[d.x], 1); atomicAdd(&g_deg[d.y], 1);
        atomicAdd(&g_deg[d.z], 1); atomicAdd(&g_deg[d.w], 1);
    } else {
        for (int e = e4; e < E && e >= 0; e++) atomicAdd(&g_deg[dst[e]], 1);
    }
}

// K2: 4 threads per node (one float4 chunk each): dinv; pre = emb[x[v]]*dinv;
//     agg1 = pre (self-loop seed); reset deg. Node's 4 threads share a warp
//     and are convergent at the load, so read-before-lane0-reset is race-free.
__global__ void k_pre(const int* __restrict__ x, const float* __restrict__ emb,
                      int n) {
    int t = blockIdx.x * blockDim.x + threadIdx.x;
    int v = t >> 2, q = t & 3;
    if (v >= n) return;
    int d = g_deg[v];
    float dinv = rsqrtf((float)(d + 1));
    if (q == 0) { g_deg[v] = 0; g_dinv[v] = dinv; }
    int xr = __ldg(&x[v]);
    float4 e = reinterpret_cast<const float4*>(emb)[(size_t)xr * 4 + q];
    float4 p = make_float4(e.x * dinv, e.y * dinv, e.z * dinv, e.w * dinv);
    reinterpret_cast<float4*>(g_pre )[(size_t)v * 4 + q] = p;
    reinterpret_cast<float4*>(g_agg1)[(size_t)v * 4 + q] = p;
}

// K3/K5: edge scatter in 16-dim space: 4 threads per edge, red.v4 per thread.
template <int LAYER>
__global__ void k_scatter(const int* __restrict__ src, const int* __restrict__ dst,
                          int E) {
    const float* in  = (LAYER == 1) ? g_pre  : g_hs2;
    float*       out = (LAYER == 1) ? g_agg1 : g_agg2;

    long long t = (long long)blockIdx.x * blockDim.x + threadIdx.x;
    int e = (int)(t >> 2);
    if (e >= E) return;
    int c = (int)t & 3;

    int s = __ldg(&src[e]);
    int d = __ldg(&dst[e]);

    float4 v = *reinterpret_cast<const float4*>(in + ((size_t)s << 4) + c * 4);
    float* p = out + ((size_t)d << 4) + c * 4;
    asm volatile("red.global.add.v4.f32 [%0], {%1,%2,%3,%4};"
                 :: "l"(p), "f"(v.x), "f"(v.y), "f"(v.z), "f"(v.w) : "memory");
}

// K4: thread per node. Weights in shared as packed f32-pairs, read via
//     LDS.128 (ulonglong2 = 4 floats = 2 f32x2 pairs); math via fma.rn.f32x2
//     (512 packed FMA per thread instead of 1024 scalar FFMA).
//     a = agg1*dinv; r = relu(a@W1+b1); hs2 = agg2 = (r@W2)*dinv.
__global__ void k_mid(const float* __restrict__ W1, const float* __restrict__ b1,
                      const float* __restrict__ W2, int n) {
    // W1: 16x32 floats = 512 floats = 128 ulonglong2 (8 per row).
    // W2: 32x16 floats = 512 floats = 128 ulonglong2 (4 per row).
    __shared__ ulonglong2 W1s[D_IN * D_HID / 4];       // 128
    __shared__ ulonglong2 W2s[D_HID * D_OUT / 4];      // 128
    __shared__ unsigned long long b1s[D_HID / 2];      // 16 pairs
    for (int t = threadIdx.x; t < D_IN * D_HID / 4; t += blockDim.x)
        W1s[t] = reinterpret_cast<const ulonglong2*>(W1)[t];
    for (int t = threadIdx.x; t < D_HID * D_OUT / 4; t += blockDim.x)
        W2s[t] = reinterpret_cast<const ulonglong2*>(W2)[t];
    if (threadIdx.x < D_HID / 2)
        b1s[threadIdx.x] = reinterpret_cast<const unsigned long long*>(b1)[threadIdx.x];
    __syncthreads();

    int v = blockIdx.x * blockDim.x + threadIdx.x;
    if (v >= n) return;

    float dinv = g_dinv[v];
    float a[D_IN];
    const float4* ar = reinterpret_cast<const float4*>(g_agg1 + (size_t)v * D_IN);
#pragma unroll
    for (int q = 0; q < D_IN / 4; q++) {
        float4 t = ar[q];
        a[q*4+0] = t.x * dinv; a[q*4+1] = t.y * dinv;
        a[q*4+2] = t.z * dinv; a[q*4+3] = t.w * dinv;
    }

    // r2[j2] accumulates (r[2*j2], r[2*j2+1]) packed.  256 fma2.
    unsigned long long r2[D_HID / 2];
#pragma unroll
    for (int j2 = 0; j2 < D_HID / 2; j2++) r2[j2] = b1s[j2];
#pragma unroll
    for (int k = 0; k < D_IN; k++) {
        unsigned long long ap;
        PACK_F32X2(ap, a[k], a[k]);
#pragma unroll
        for (int j4 = 0; j4 < D_HID / 4; j4++) {      // 8 ulonglong2 per W1 row
            ulonglong2 w = W1s[k * (D_HID / 4) + j4];
            FMA_F32X2(r2[2*j4+0], ap, w.x, r2[2*j4+0]);
            FMA_F32X2(r2[2*j4+1], ap, w.y, r2[2*j4+1]);
        }
    }
    // Unpack + relu.
    float r[D_HID];
#pragma unroll
    for (int j2 = 0; j2 < D_HID / 2; j2++) {
        float lo, hi;
        UNPACK_F32X2(lo, hi, r2[j2]);
        r[2*j2+0] = fmaxf(lo, 0.f);
        r[2*j2+1] = fmaxf(hi, 0.f);
    }

    // h2[j2] accumulates (h[2*j2], h[2*j2+1]).  256 fma2.
    unsigned long long h2[D_OUT / 2];
#pragma unroll
    for (int j2 = 0; j2 < D_OUT / 2; j2++) h2[j2] = 0ull;
#pragma unroll
    for (int k = 0; k < D_HID; k++) {
        unsigned long long rp;
        PACK_F32X2(rp, r[k], r[k]);
#pragma unroll
        for (int j4 = 0; j4 < D_OUT / 4; j4++) {      // 4 ulonglong2 per W2 row
            ulonglong2 w = W2s[k * (D_OUT / 4) + j4];
            FMA_F32X2(h2[2*j4+0], rp, w.x, h2[2*j4+0]);
            FMA_F32X2(h2[2*j4+1], rp, w.y, h2[2*j4+1]);
        }
    }

    float h[D_OUT];
#pragma unroll
    for (int j2 = 0; j2 < D_OUT / 2; j2++) {
        float lo, hi;
        UNPACK_F32X2(lo, hi, h2[j2]);
        h[2*j2+0] = lo * dinv;
        h[2*j2+1] = hi * dinv;
    }

    float4* hr = reinterpret_cast<float4*>(g_hs2  + (size_t)v * D_OUT);
    float4* gr = reinterpret_cast<float4*>(g_agg2 + (size_t)v * D_OUT);
#pragma unroll
    for (int q = 0; q < D_OUT / 4; q++) {
        float4 t = make_float4(h[q*4+0], h[q*4+1], h[q*4+2], h[q*4+3]);
        hr[q] = t;
        gr[q] = t;
    }
}

// K6: 4 threads per node: out = agg2*dinv + b2.
__global__ void k_post(const float* __restrict__ b2, float* __restrict__ out, int n) {
    int t = blockIdx.x * blockDim.x + threadIdx.x;
    int v = t >> 2, q = t & 3;
    if (v >= n) return;
    float dinv = g_dinv[v];
    float4 a = reinterpret_cast<const float4*>(g_agg2)[(size_t)v * 4 + q];
    float4 bb = __ldg(reinterpret_cast<const float4*>(b2) + q);
    reinterpret_cast<float4*>(out)[(size_t)v * 4 + q] =
        make_float4(dinv * a.x + bb.x, dinv * a.y + bb.y,
                    dinv * a.z + bb.z, dinv * a.w + bb.w);
}

extern "C" void kernel_launch(void* const* d_in, const int* in_sizes, int n_in,
                              void* d_out, int out_size) {
    const int*   x   = (const int*)  d_in[0];
    const int*   ei  = (const int*)  d_in[1];   // [2, E]: src then dst
    const float* emb = (const float*)d_in[2];
    const float* W1  = (const float*)d_in[3];
    const float* b1  = (const float*)d_in[4];
    const float* W2  = (const float*)d_in[5];
    const float* b2  = (const float*)d_in[6];
    float* out = (float*)d_out;

    int n = in_sizes[0];
    int E = in_sizes[1] / 2;
    const int* src = ei;
    const int* dst = ei + E;

    const int B = 256;
    long long et = (long long)E * 4;
    int nb_edge  = (int)((et + B - 1) / B);
    int nb_node4 = (n * 4 + B - 1) / B;

    k_deg       <<<(E / 4 + B - 1) / B + 1, B>>>(dst, E);
    k_pre       <<<nb_node4, B>>>(x, emb, n);
    k_scatter<1><<<nb_edge, B>>>(src, dst, E);
    k_mid       <<<(n + 127) / 128, 128>>>(W1, b1, W2, n);
    k_scatter<2><<<nb_edge, B>>>(src, dst, E);
    k_post      <<<nb_node4, B>>>(b2, out, n);
}